// round 9
// baseline (speedup 1.0000x reference)
#include <cuda_runtime.h>
#include <cuda_bf16.h>
#include <math.h>
#include <stdint.h>

#define NJ 33
#define FD 256
#define MAXB 4096
#define NNMAX (MAXB*NJ)
#define MAXE 165

typedef uint32_t u32;
typedef uint64_t u64;

// ---- scratch (no allocations allowed) ----
__device__ float g_bufA[(size_t)NNMAX*FD];
__device__ float g_bufB[(size_t)NNMAX*FD];
__device__ float g_sum[FD], g_sumsq[FD];
__device__ float g_scale[FD], g_shift[FD];
__device__ int   g_rp[NJ+1];
__device__ int   g_ci[MAXE];
__device__ float g_av[MAXE];
__device__ float g_acol[NJ];
__device__ float g_whc[FD*4];
__device__ float g_bhc[4];
// Weights pre-packed in m16n8k16 B-fragment order, bf16 hi/lo split.
// Index: (nf*16 + ks)*32 + lane ; nf = n/8 (32), ks = k/16 (16).
__device__ u64 g_wb_hi[3][16384];
__device__ u64 g_wb_lo[3][16384];

// ============================================================
// Prep: CSR of normalized adjacency (shared by all graphs),
// a_col pooling weights, fused head whc = wh@wc.
// ============================================================
__global__ void prep_kernel(const int* __restrict__ src, const int* __restrict__ dst,
                            int epg,
                            const float* __restrict__ wh, const float* __restrict__ wc,
                            const float* __restrict__ bh, const float* __restrict__ bc) {
    __shared__ float s_dinv[NJ];
    int tid = threadIdx.x;
    if (tid < NJ) {
        int d = 0;
        for (int e = 0; e < epg; ++e) d += (dst[e] == tid);
        s_dinv[tid] = rsqrtf((float)d);
    }
    if (tid < FD) { g_sum[tid] = 0.f; g_sumsq[tid] = 0.f; }
    __syncthreads();
    if (tid == 0) {
        int pos = 0;
        for (int j = 0; j < NJ; ++j) {
            g_rp[j] = pos;
            for (int e = 0; e < epg && pos < MAXE; ++e) {
                if (dst[e] == j) {
                    int r = src[e];
                    g_ci[pos] = r;
                    g_av[pos] = s_dinv[r] * s_dinv[j];
                    pos++;
                }
            }
        }
        g_rp[NJ] = pos;
    }
    if (tid < NJ) {
        float s = 0.f;
        for (int e = 0; e < epg; ++e)
            if (src[e] == tid) s += s_dinv[tid] * s_dinv[dst[e]];
        g_acol[tid] = s / (float)NJ;
    }
    for (int idx = tid; idx < FD*4; idx += blockDim.x) {
        int k = idx >> 2, l = idx & 3;
        float s = 0.f;
        for (int c = 0; c < FD; ++c) s += wh[k*FD + c] * wc[c*4 + l];
        g_whc[idx] = s;
    }
    if (tid < 4) {
        float s = 0.f;
        for (int c = 0; c < FD; ++c) s += bh[c] * wc[c*4 + tid];
        g_bhc[tid] = s + bc[tid];
    }
}

// W[k][n] fp32 -> fragment-ordered bf16 hi/lo pack.
__global__ void convw_kernel(const float* __restrict__ W, int layer) {
    const int i = blockIdx.x * 256 + threadIdx.x;       // 0..16383
    const int lane = i & 31;
    const int ks = (i >> 5) & 15;
    const int nf = i >> 9;
    const int n = nf*8 + (lane >> 2);
    const int k = ks*16 + (lane & 3)*2;
    float e0 = W[k*FD + n],     e1 = W[(k+1)*FD + n];
    float e2 = W[(k+8)*FD + n], e3 = W[(k+9)*FD + n];
    __nv_bfloat162 h0 = __floats2bfloat162_rn(e0, e1);
    __nv_bfloat162 h1 = __floats2bfloat162_rn(e2, e3);
    __nv_bfloat162 l0 = __floats2bfloat162_rn(e0 - __low2float(h0), e1 - __high2float(h0));
    __nv_bfloat162 l1 = __floats2bfloat162_rn(e2 - __low2float(h1), e3 - __high2float(h1));
    g_wb_hi[layer][i] = (u64)(*(u32*)&h0) | ((u64)(*(u32*)&h1) << 32);
    g_wb_lo[layer][i] = (u64)(*(u32*)&l0) | ((u64)(*(u32*)&l1) << 32);
}

// ============================================================
// Pass A: Y = pre(Z) @ W via mma.sync m16n8k16 bf16 (3-term split).
// Block tile 128x256, 16 warps = 2m x 8n, warp tile 64x32.
// K chunked by 128 through smem (A hi/lo bf16, 272B row stride).
// B fragments software-pipelined (next k-step prefetched into regs).
// ============================================================
#define SM_HI 0
#define SM_LO 34816
#define SM_SC 69632
#define SM_SH 70656
#define GEMM_SMEM 71680
#define ASTRIDE 272     // bytes per A smem row (256 data + 16 pad)

__device__ __forceinline__ void mma16816(float* d, u32 a0, u32 a1, u32 a2, u32 a3,
                                         u32 b0, u32 b1) {
    asm volatile(
        "mma.sync.aligned.m16n8k16.row.col.f32.bf16.bf16.f32 "
        "{%0,%1,%2,%3}, {%4,%5,%6,%7}, {%8,%9}, {%0,%1,%2,%3};"
        : "+f"(d[0]), "+f"(d[1]), "+f"(d[2]), "+f"(d[3])
        : "r"(a0), "r"(a1), "r"(a2), "r"(a3), "r"(b0), "r"(b1));
}

__global__ void __launch_bounds__(512)
gemm_kernel(const float* __restrict__ x_ext, int mode, int layer, int Bn, int NN) {
    extern __shared__ char smem[];
    const int tid  = threadIdx.x;
    const int lane = tid & 31, wid = tid >> 5;     // wid 0..15
    const int wm = wid & 1, wn = wid >> 1;          // 2m x 8n
    const int m0 = blockIdx.x * 128;

    // scale/shift to smem (used in mode 1)
    if (tid < 256) {
        *(float*)(smem + SM_SC + tid*4) = g_scale[tid];
        *(float*)(smem + SM_SH + tid*4) = g_shift[tid];
    }

    float acc[4][4][4];
    #pragma unroll
    for (int mf = 0; mf < 4; ++mf)
        #pragma unroll
        for (int nf = 0; nf < 4; ++nf)
            #pragma unroll
            for (int q = 0; q < 4; ++q) acc[mf][nf][q] = 0.f;

    const u64* __restrict__ WBH = g_wb_hi[layer];
    const u64* __restrict__ WBL = g_wb_lo[layer];

    // loader mapping: row = tid>>2, quarter = tid&3 (32 k-cols each)
    const int rowl = tid >> 2, qc = tid & 3;
    const int m_ld = m0 + rowl;
    const float* srcrow;
    if (mode == 0) {
        const int j = m_ld / Bn, g = m_ld - j*Bn;
        srcrow = x_ext + ((size_t)g*NJ + j)*FD;
    } else {
        srcrow = g_bufA + (size_t)m_ld*FD;
    }
    const bool vld = (m_ld < NN);
    char* hib = smem + SM_HI + rowl*ASTRIDE + qc*64;
    char* lob = smem + SM_LO + rowl*ASTRIDE + qc*64;
    const float* ssc = (const float*)(smem + SM_SC);
    const float* ssh = (const float*)(smem + SM_SH);

    // fragment smem byte offsets (per thread)
    const int arow = wm*64 + (lane >> 2);
    const int acol = (lane & 3)*4;               // bytes within k16 step

    for (int c = 0; c < 2; ++c) {
        __syncthreads();                          // smem reusable (also covers sc/sh copy)
        // ---- stage A chunk: rows 0..127, k in [c*128, c*128+128) ----
        #pragma unroll
        for (int i = 0; i < 8; ++i) {
            const int k = c*128 + qc*32 + i*4;
            float4 v = make_float4(0.f, 0.f, 0.f, 0.f);
            if (vld) v = *(const float4*)(srcrow + k);
            if (mode == 0) {
                if (v.x != v.x) v.x = 0.f;
                if (v.y != v.y) v.y = 0.f;
                if (v.z != v.z) v.z = 0.f;
                if (v.w != v.w) v.w = 0.f;
            } else {
                v.x = fmaxf(fmaf(v.x, ssc[k],   ssh[k]),   0.f);
                v.y = fmaxf(fmaf(v.y, ssc[k+1], ssh[k+1]), 0.f);
                v.z = fmaxf(fmaf(v.z, ssc[k+2], ssh[k+2]), 0.f);
                v.w = fmaxf(fmaf(v.w, ssc[k+3], ssh[k+3]), 0.f);
            }
            __nv_bfloat162 h0 = __floats2bfloat162_rn(v.x, v.y);
            __nv_bfloat162 h1 = __floats2bfloat162_rn(v.z, v.w);
            __nv_bfloat162 l0 = __floats2bfloat162_rn(v.x - __low2float(h0), v.y - __high2float(h0));
            __nv_bfloat162 l1 = __floats2bfloat162_rn(v.z - __low2float(h1), v.w - __high2float(h1));
            *(u32*)(hib + i*8)     = *(u32*)&h0;
            *(u32*)(hib + i*8 + 4) = *(u32*)&h1;
            *(u32*)(lob + i*8)     = *(u32*)&l0;
            *(u32*)(lob + i*8 + 4) = *(u32*)&l1;
        }
        __syncthreads();

        // ---- software-pipelined B fragments across k-steps ----
        u64 bhv[4], blv[4];                       // current k-step
        {
            const int ksa = c*8;
            #pragma unroll
            for (int nf = 0; nf < 4; ++nf) {
                const int idx = ((wn*4 + nf)*16 + ksa)*32 + lane;
                bhv[nf] = WBH[idx];
                blv[nf] = WBL[idx];
            }
        }
        for (int ks = 0; ks < 8; ++ks) {
            u64 nbh[4], nbl[4];                   // prefetch next k-step
            if (ks < 7) {
                const int ksa = c*8 + ks + 1;
                #pragma unroll
                for (int nf = 0; nf < 4; ++nf) {
                    const int idx = ((wn*4 + nf)*16 + ksa)*32 + lane;
                    nbh[nf] = WBH[idx];
                    nbl[nf] = WBL[idx];
                }
            }
            #pragma unroll
            for (int mf = 0; mf < 4; ++mf) {
                const int ro = (arow + mf*16)*ASTRIDE + ks*32 + acol;
                const u32 ah0 = *(const u32*)(smem + SM_HI + ro);
                const u32 ah1 = *(const u32*)(smem + SM_HI + ro + 8*ASTRIDE);
                const u32 ah2 = *(const u32*)(smem + SM_HI + ro + 16);
                const u32 ah3 = *(const u32*)(smem + SM_HI + ro + 8*ASTRIDE + 16);
                const u32 al0 = *(const u32*)(smem + SM_LO + ro);
                const u32 al1 = *(const u32*)(smem + SM_LO + ro + 8*ASTRIDE);
                const u32 al2 = *(const u32*)(smem + SM_LO + ro + 16);
                const u32 al3 = *(const u32*)(smem + SM_LO + ro + 8*ASTRIDE + 16);
                #pragma unroll
                for (int nf = 0; nf < 4; ++nf) {
                    const u32 b0 = (u32)bhv[nf], b1 = (u32)(bhv[nf] >> 32);
                    const u32 c0 = (u32)blv[nf], c1 = (u32)(blv[nf] >> 32);
                    mma16816(acc[mf][nf], ah0, ah1, ah2, ah3, b0, b1);
                    mma16816(acc[mf][nf], ah0, ah1, ah2, ah3, c0, c1);
                    mma16816(acc[mf][nf], al0, al1, al2, al3, b0, b1);
                }
            }
            if (ks < 7) {
                #pragma unroll
                for (int nf = 0; nf < 4; ++nf) { bhv[nf] = nbh[nf]; blv[nf] = nbl[nf]; }
            }
        }
    }

    // ---- store: d0,d1 -> (r, col..col+1), d2,d3 -> (r+8, col..col+1) ----
    const int rbase = m0 + wm*64 + (lane >> 2);
    const int cbase = wn*32 + (lane & 3)*2;
    #pragma unroll
    for (int mf = 0; mf < 4; ++mf) {
        const int r0 = rbase + mf*16;
        #pragma unroll
        for (int nf = 0; nf < 4; ++nf) {
            const int cc = cbase + nf*8;
            if (r0 < NN)
                *(float2*)(g_bufB + (size_t)r0*FD + cc) = make_float2(acc[mf][nf][0], acc[mf][nf][1]);
            if (r0 + 8 < NN)
                *(float2*)(g_bufB + (size_t)(r0+8)*FD + cc) = make_float2(acc[mf][nf][2], acc[mf][nf][3]);
        }
    }
}

// ============================================================
// Pass B: Z = A_hat @ Y + bias (per graph), accumulate BN sums.
// Buffers joint-major: row m = j*Bn + g.
// ============================================================
__global__ void __launch_bounds__(256)
sparse_kernel(const float* __restrict__ bias, int Bn) {
    __shared__ float sy[NJ*FD];
    __shared__ int   srp[NJ+1];
    __shared__ int   sci[MAXE];
    __shared__ float sav[MAXE];
    const int tid = threadIdx.x;
    const int g   = blockIdx.x;

    if (tid <= NJ) srp[tid] = g_rp[tid];
    if (tid < MAXE) { sci[tid] = g_ci[tid]; sav[tid] = g_av[tid]; }
    #pragma unroll
    for (int r = 0; r < NJ; ++r)
        sy[r*FD + tid] = g_bufB[((size_t)r*Bn + g)*FD + tid];
    __syncthreads();

    const float bf = bias[tid];
    float s1 = 0.f, s2 = 0.f;
    #pragma unroll 4
    for (int j = 0; j < NJ; ++j) {
        float z = bf;
        const int p1 = srp[j+1];
        for (int p = srp[j]; p < p1; ++p)
            z = fmaf(sav[p], sy[sci[p]*FD + tid], z);
        g_bufA[((size_t)j*Bn + g)*FD + tid] = z;
        s1 += z;
        s2 = fmaf(z, z, s2);
    }
    atomicAdd(&g_sum[tid], s1);
    atomicAdd(&g_sumsq[tid], s2);
}

// ============================================================
__global__ void stats_kernel(const float* __restrict__ g, const float* __restrict__ be,
                             float inv_nn) {
    int tid = threadIdx.x;
    float mu  = g_sum[tid] * inv_nn;
    float var = g_sumsq[tid] * inv_nn - mu * mu;
    float rs  = rsqrtf(var + 1e-5f);
    float sc  = rs * g[tid];
    g_scale[tid] = sc;
    g_shift[tid] = be[tid] - mu * sc;
    g_sum[tid] = 0.f; g_sumsq[tid] = 0.f;
}

// ============================================================
// Head: BN2+ReLU -> a_col^T h (per graph) -> @ (wh@wc) + bhc
// ============================================================
__global__ void __launch_bounds__(256)
final_kernel(float* __restrict__ out, int Bn) {
    __shared__ float s_acol[NJ];
    __shared__ float s_red[8][4];
    const int tid = threadIdx.x;
    const int b   = blockIdx.x;
    if (tid < NJ) s_acol[tid] = g_acol[tid];
    __syncthreads();

    const float sc  = g_scale[tid];
    const float shf = g_shift[tid];

    float v = 0.f;
    #pragma unroll
    for (int r = 0; r < NJ; ++r) {
        float x = g_bufA[((size_t)r*Bn + b)*FD + tid];
        x = fmaxf(fmaf(x, sc, shf), 0.f);
        v = fmaf(s_acol[r], x, v);
    }
    float4 w = ((const float4*)g_whc)[tid];
    float p0 = v * w.x, p1 = v * w.y, p2 = v * w.z, p3 = v * w.w;
    #pragma unroll
    for (int o = 16; o; o >>= 1) {
        p0 += __shfl_down_sync(0xffffffffu, p0, o);
        p1 += __shfl_down_sync(0xffffffffu, p1, o);
        p2 += __shfl_down_sync(0xffffffffu, p2, o);
        p3 += __shfl_down_sync(0xffffffffu, p3, o);
    }
    const int lane = tid & 31, wid = tid >> 5;
    if (lane == 0) { s_red[wid][0] = p0; s_red[wid][1] = p1; s_red[wid][2] = p2; s_red[wid][3] = p3; }
    __syncthreads();
    if (tid < 4) {
        float s = 0.f;
        #pragma unroll
        for (int w8 = 0; w8 < 8; ++w8) s += s_red[w8][tid];
        out[b*4 + tid] = s + g_bhc[tid];
    }
}

// ============================================================
extern "C" void kernel_launch(void* const* d_in, const int* in_sizes, int n_in,
                              void* d_out, int out_size) {
    const float* x   = (const float*)d_in[0];
    const float* w0  = (const float*)d_in[1];
    const float* b0  = (const float*)d_in[2];
    const float* gg0 = (const float*)d_in[3];
    const float* be0 = (const float*)d_in[4];
    const float* w1  = (const float*)d_in[5];
    const float* b1  = (const float*)d_in[6];
    const float* gg1 = (const float*)d_in[7];
    const float* be1 = (const float*)d_in[8];
    const float* w2  = (const float*)d_in[9];
    const float* b2  = (const float*)d_in[10];
    const float* gg2 = (const float*)d_in[11];
    const float* be2 = (const float*)d_in[12];
    const float* wh  = (const float*)d_in[13];
    const float* bh  = (const float*)d_in[14];
    const float* wc  = (const float*)d_in[15];
    const float* bc  = (const float*)d_in[16];
    const int*   src = (const int*)d_in[17];
    const int*   dst = (const int*)d_in[18];
    float* out = (float*)d_out;

    const int B   = in_sizes[0] / (NJ * FD);
    const int NN  = B * NJ;
    const int epg = in_sizes[17] / B;
    const float inv_nn = 1.0f / (float)NN;
    const int gemm_grid = (NN + 127) / 128;

    static int smem_set = 0;
    if (!smem_set) {
        cudaFuncSetAttribute(gemm_kernel, cudaFuncAttributeMaxDynamicSharedMemorySize, GEMM_SMEM);
        smem_set = 1;
    }

    // Launch order chosen so gemm_kernel is the 4th launch (ncu capture slot).
    prep_kernel<<<1, 256>>>(src, dst, epg, wh, wc, bh, bc);
    convw_kernel<<<64, 256>>>(w0, 0);
    convw_kernel<<<64, 256>>>(w1, 1);

    gemm_kernel<<<gemm_grid, 512, GEMM_SMEM>>>(x, 0, 0, B, NN);
    sparse_kernel<<<B, 256>>>(b0, B);
    stats_kernel<<<1, 256>>>(gg0, be0, inv_nn);

    convw_kernel<<<64, 256>>>(w2, 2);

    gemm_kernel<<<gemm_grid, 512, GEMM_SMEM>>>(nullptr, 1, 1, B, NN);
    sparse_kernel<<<B, 256>>>(b1, B);
    stats_kernel<<<1, 256>>>(gg1, be1, inv_nn);

    gemm_kernel<<<gemm_grid, 512, GEMM_SMEM>>>(nullptr, 1, 2, B, NN);
    sparse_kernel<<<B, 256>>>(b2, B);
    stats_kernel<<<1, 256>>>(gg2, be2, inv_nn);

    final_kernel<<<B, 256>>>(out, B);
}

// round 12
// speedup vs baseline: 1.1884x; 1.1884x over previous
#include <cuda_runtime.h>
#include <cuda_bf16.h>
#include <math.h>
#include <stdint.h>

#define NJ 33
#define FD 256
#define MAXB 4096
#define NNMAX (MAXB*NJ)
#define MAXE 165

typedef uint32_t u32;
typedef uint64_t u64;

// ---- scratch (no allocations allowed) ----
__device__ float g_bufA[(size_t)NNMAX*FD];
__device__ float g_sum[FD], g_sumsq[FD];
__device__ float g_scale[FD], g_shift[FD];
__device__ int   g_rp[NJ+1];
__device__ int   g_ci[MAXE];
__device__ float g_av[MAXE];
__device__ float g_acol[NJ];
__device__ float g_whc[FD*4];
__device__ float g_bhc[4];
// Weights pre-packed in m16n8k16 B-fragment order, bf16 hi/lo split.
__device__ u64 g_wb_hi[3][16384];
__device__ u64 g_wb_lo[3][16384];

// ============================================================
// Prep (parallelized CSR build)
// ============================================================
__global__ void prep_kernel(const int* __restrict__ src, const int* __restrict__ dst,
                            int epg,
                            const float* __restrict__ wh, const float* __restrict__ wc,
                            const float* __restrict__ bh, const float* __restrict__ bc) {
    __shared__ int   s_s[MAXE], s_d[MAXE];
    __shared__ float s_dinv[NJ];
    __shared__ int   s_cnt[NJ];
    const int tid = threadIdx.x;
    if (tid < epg && tid < MAXE) { s_s[tid] = src[tid]; s_d[tid] = dst[tid]; }
    if (tid < FD) { g_sum[tid] = 0.f; g_sumsq[tid] = 0.f; }
    __syncthreads();
    if (tid < NJ) {
        int d = 0;
        for (int e = 0; e < epg; ++e) d += (s_d[e] == tid);
        s_cnt[tid] = d;
        s_dinv[tid] = rsqrtf((float)d);
    }
    __syncthreads();
    if (tid == 0) {
        int pos = 0;
        for (int j = 0; j < NJ; ++j) { g_rp[j] = pos; pos += s_cnt[j]; }
        g_rp[NJ] = pos;
    }
    __syncthreads();
    if (tid < NJ) {
        int pos = g_rp[tid];
        float s = 0.f;
        for (int e = 0; e < epg; ++e) {
            if (s_d[e] == tid) {
                const int r = s_s[e];
                g_ci[pos] = r;
                g_av[pos] = s_dinv[r] * s_dinv[tid];
                pos++;
            }
            if (s_s[e] == tid) s += s_dinv[tid] * s_dinv[s_d[e]];
        }
        g_acol[tid] = s / (float)NJ;
    }
    for (int idx = tid; idx < FD*4; idx += blockDim.x) {
        int k = idx >> 2, l = idx & 3;
        float s = 0.f;
        for (int c = 0; c < FD; ++c) s += wh[k*FD + c] * wc[c*4 + l];
        g_whc[idx] = s;
    }
    if (tid < 4) {
        float s = 0.f;
        for (int c = 0; c < FD; ++c) s += bh[c] * wc[c*4 + tid];
        g_bhc[tid] = s + bc[tid];
    }
}

// W[k][n] fp32 -> fragment-ordered bf16 hi/lo pack.
__global__ void convw_kernel(const float* __restrict__ W, int layer) {
    const int i = blockIdx.x * 256 + threadIdx.x;       // 0..16383
    const int lane = i & 31;
    const int ks = (i >> 5) & 15;
    const int nf = i >> 9;
    const int n = nf*8 + (lane >> 2);
    const int k = ks*16 + (lane & 3)*2;
    float e0 = W[k*FD + n],     e1 = W[(k+1)*FD + n];
    float e2 = W[(k+8)*FD + n], e3 = W[(k+9)*FD + n];
    __nv_bfloat162 h0 = __floats2bfloat162_rn(e0, e1);
    __nv_bfloat162 h1 = __floats2bfloat162_rn(e2, e3);
    __nv_bfloat162 l0 = __floats2bfloat162_rn(e0 - __low2float(h0), e1 - __high2float(h0));
    __nv_bfloat162 l1 = __floats2bfloat162_rn(e2 - __low2float(h1), e3 - __high2float(h1));
    g_wb_hi[layer][i] = (u64)(*(u32*)&h0) | ((u64)(*(u32*)&h1) << 32);
    g_wb_lo[layer][i] = (u64)(*(u32*)&l0) | ((u64)(*(u32*)&l1) << 32);
}

// ============================================================
// Fully fused layer: pre(Z) @ W  then  A_hat @ Y + b, BN sums.
// Graph-major [g][j][f]: block = 4 graphs = 132 rows (pad 144).
// 16 warps = 1m x 16n; warp tile 144x16 (9 m16 x 2 n8 frags).
// in_sel: 0 = x_ext (nan_to_num), 1 = g_bufA (BN+relu) -- pointer
// resolved IN DEVICE CODE (host cannot pass __device__ symbols).
// ============================================================
#define ASTRIDE 272
#define A_HI 0
#define A_LO 39168          /* 144*272 */
#define SM_SC 147456        /* ybuf occupies [0,147456) after MMA */
#define SM_SH 148480
#define SM_RP 149504
#define SM_CI 149664
#define SM_AV 150328
#define FUSED_SMEM 151040

__device__ __forceinline__ void mma16816(float* d, u32 a0, u32 a1, u32 a2, u32 a3,
                                         u32 b0, u32 b1) {
    asm volatile(
        "mma.sync.aligned.m16n8k16.row.col.f32.bf16.bf16.f32 "
        "{%0,%1,%2,%3}, {%4,%5,%6,%7}, {%8,%9}, {%0,%1,%2,%3};"
        : "+f"(d[0]), "+f"(d[1]), "+f"(d[2]), "+f"(d[3])
        : "r"(a0), "r"(a1), "r"(a2), "r"(a3), "r"(b0), "r"(b1));
}

__global__ void __launch_bounds__(512)
fused_kernel(const float* __restrict__ x_ext, const float* __restrict__ bias,
             int in_sel /*0 = x + nan_to_num, 1 = g_bufA + BN+relu*/,
             int layer, int Bn) {
    extern __shared__ char smem[];
    const int tid  = threadIdx.x;
    const int lane = tid & 31, wid = tid >> 5;     // 16 warps
    const int wn   = wid;                           // n stripe: cols [wn*16, wn*16+16)
    const int blk  = blockIdx.x;
    const int m0   = blk * 132;                     // global row base (graph-major)
    const int NNv  = Bn * NJ;
    const int mode = in_sel;

    const float* in = (in_sel == 0) ? x_ext : (const float*)g_bufA;

    // stage BN params + CSR into smem (regions above ybuf; persist whole kernel)
    if (tid < 256) {
        *(float*)(smem + SM_SC + tid*4) = g_scale[tid];
        *(float*)(smem + SM_SH + tid*4) = g_shift[tid];
    }
    if (tid <= NJ) *(int*)(smem + SM_RP + tid*4) = g_rp[tid];
    if (tid < MAXE) {
        *(int*)  (smem + SM_CI + tid*4) = g_ci[tid];
        *(float*)(smem + SM_AV + tid*4) = g_av[tid];
    }

    float acc[9][2][4];
    #pragma unroll
    for (int mf = 0; mf < 9; ++mf)
        #pragma unroll
        for (int nf = 0; nf < 2; ++nf)
            #pragma unroll
            for (int q = 0; q < 4; ++q) acc[mf][nf][q] = 0.f;

    const u64* __restrict__ WBH = g_wb_hi[layer];
    const u64* __restrict__ WBL = g_wb_lo[layer];

    const int rowl = tid >> 2, qc = tid & 3;        // loader: 128 rows x 4 quarters
    const float* ssc = (const float*)(smem + SM_SC);
    const float* ssh = (const float*)(smem + SM_SH);

    const int arowb = (lane >> 2);
    const int acol  = (lane & 3)*4;                 // bytes within k16 step

    for (int c = 0; c < 2; ++c) {
        __syncthreads();
        // ---- stage A: rows 0..143 (132 valid), k in [c*128, +128) ----
        #pragma unroll
        for (int rr = 0; rr < 2; ++rr) {
            const int r = rowl + rr*128;
            if (rr == 1 && rowl >= 16) break;
            const bool ok = (r < 132) && (m0 + r < NNv);
            char* hib = smem + A_HI + r*ASTRIDE + qc*64;
            char* lob = smem + A_LO + r*ASTRIDE + qc*64;
            const float* srcrow = in + (size_t)(m0 + r) * FD;
            #pragma unroll
            for (int i = 0; i < 8; ++i) {
                const int k = c*128 + qc*32 + i*4;
                float4 v = make_float4(0.f, 0.f, 0.f, 0.f);
                if (ok) {
                    v = *(const float4*)(srcrow + k);
                    if (mode == 0) {
                        if (v.x != v.x) v.x = 0.f;
                        if (v.y != v.y) v.y = 0.f;
                        if (v.z != v.z) v.z = 0.f;
                        if (v.w != v.w) v.w = 0.f;
                    } else {
                        v.x = fmaxf(fmaf(v.x, ssc[k],   ssh[k]),   0.f);
                        v.y = fmaxf(fmaf(v.y, ssc[k+1], ssh[k+1]), 0.f);
                        v.z = fmaxf(fmaf(v.z, ssc[k+2], ssh[k+2]), 0.f);
                        v.w = fmaxf(fmaf(v.w, ssc[k+3], ssh[k+3]), 0.f);
                    }
                }
                __nv_bfloat162 h0 = __floats2bfloat162_rn(v.x, v.y);
                __nv_bfloat162 h1 = __floats2bfloat162_rn(v.z, v.w);
                __nv_bfloat162 l0 = __floats2bfloat162_rn(v.x - __low2float(h0), v.y - __high2float(h0));
                __nv_bfloat162 l1 = __floats2bfloat162_rn(v.z - __low2float(h1), v.w - __high2float(h1));
                *(u32*)(hib + i*8)     = *(u32*)&h0;
                *(u32*)(hib + i*8 + 4) = *(u32*)&h1;
                *(u32*)(lob + i*8)     = *(u32*)&l0;
                *(u32*)(lob + i*8 + 4) = *(u32*)&l1;
            }
        }
        __syncthreads();

        for (int ks = 0; ks < 8; ++ks) {
            const int ksa = c*8 + ks;
            const u64 vh0 = WBH[((wn*2 + 0)*16 + ksa)*32 + lane];
            const u64 vl0 = WBL[((wn*2 + 0)*16 + ksa)*32 + lane];
            const u64 vh1 = WBH[((wn*2 + 1)*16 + ksa)*32 + lane];
            const u64 vl1 = WBL[((wn*2 + 1)*16 + ksa)*32 + lane];
            #pragma unroll
            for (int mf = 0; mf < 9; ++mf) {
                const int ro = (mf*16 + arowb)*ASTRIDE + ks*32 + acol;
                const u32 ah0 = *(const u32*)(smem + A_HI + ro);
                const u32 ah1 = *(const u32*)(smem + A_HI + ro + 8*ASTRIDE);
                const u32 ah2 = *(const u32*)(smem + A_HI + ro + 16);
                const u32 ah3 = *(const u32*)(smem + A_HI + ro + 8*ASTRIDE + 16);
                const u32 al0 = *(const u32*)(smem + A_LO + ro);
                const u32 al1 = *(const u32*)(smem + A_LO + ro + 8*ASTRIDE);
                const u32 al2 = *(const u32*)(smem + A_LO + ro + 16);
                const u32 al3 = *(const u32*)(smem + A_LO + ro + 8*ASTRIDE + 16);
                mma16816(acc[mf][0], ah0, ah1, ah2, ah3, (u32)vh0, (u32)(vh0 >> 32));
                mma16816(acc[mf][0], ah0, ah1, ah2, ah3, (u32)vl0, (u32)(vl0 >> 32));
                mma16816(acc[mf][0], al0, al1, al2, al3, (u32)vh0, (u32)(vh0 >> 32));
                mma16816(acc[mf][1], ah0, ah1, ah2, ah3, (u32)vh1, (u32)(vh1 >> 32));
                mma16816(acc[mf][1], ah0, ah1, ah2, ah3, (u32)vl1, (u32)(vl1 >> 32));
                mma16816(acc[mf][1], al0, al1, al2, al3, (u32)vh1, (u32)(vh1 >> 32));
            }
        }
    }

    // ---- stage Y into smem (overwrites A region) ----
    __syncthreads();
    float2* yb = (float2*)smem;                     // [row*128 + colpair], 144 rows
    const int cpb = wn*8 + (lane & 3);
    #pragma unroll
    for (int mf = 0; mf < 9; ++mf) {
        const int r0 = mf*16 + arowb;
        #pragma unroll
        for (int nf = 0; nf < 2; ++nf) {
            const int cpi = cpb + nf*4;
            yb[ r0     *128 + cpi] = make_float2(acc[mf][nf][0], acc[mf][nf][1]);
            yb[(r0 + 8)*128 + cpi] = make_float2(acc[mf][nf][2], acc[mf][nf][3]);
        }
    }
    __syncthreads();

    // ---- sparse A_hat epilogue + bias + BN sums ----
    const int cp = tid & 127, gi = tid >> 7;        // 4 graphs, 128 col-pairs
    const int g0 = blk*4 + gi;
    if (g0 < Bn) {
        const int*   srp = (const int*)(smem + SM_RP);
        const int*   sci = (const int*)(smem + SM_CI);
        const float* sav = (const float*)(smem + SM_AV);
        const float2 bia = ((const float2*)bias)[cp];
        float s1x = 0.f, s1y = 0.f, s2x = 0.f, s2y = 0.f;
        float* outg = g_bufA + (size_t)(m0 + gi*NJ) * FD;
        for (int j = 0; j < NJ; ++j) {
            float zx = bia.x, zy = bia.y;
            const int p1 = srp[j+1];
            for (int p = srp[j]; p < p1; ++p) {
                const float  a = sav[p];
                const float2 y = yb[(gi*NJ + sci[p])*128 + cp];
                zx = fmaf(a, y.x, zx);
                zy = fmaf(a, y.y, zy);
            }
            *(float2*)(outg + j*FD + cp*2) = make_float2(zx, zy);
            s1x += zx; s1y += zy;
            s2x = fmaf(zx, zx, s2x); s2y = fmaf(zy, zy, s2y);
        }
        atomicAdd(&g_sum[2*cp],     s1x);
        atomicAdd(&g_sum[2*cp + 1], s1y);
        atomicAdd(&g_sumsq[2*cp],     s2x);
        atomicAdd(&g_sumsq[2*cp + 1], s2y);
    }
}

// ============================================================
__global__ void stats_kernel(const float* __restrict__ g, const float* __restrict__ be,
                             float inv_nn) {
    int tid = threadIdx.x;
    float mu  = g_sum[tid] * inv_nn;
    float var = g_sumsq[tid] * inv_nn - mu * mu;
    float rs  = rsqrtf(var + 1e-5f);
    float sc  = rs * g[tid];
    g_scale[tid] = sc;
    g_shift[tid] = be[tid] - mu * sc;
    g_sum[tid] = 0.f; g_sumsq[tid] = 0.f;
}

// ============================================================
// Head: BN2+ReLU -> a_col^T h (per graph, graph-major) -> whc + bhc
// ============================================================
__global__ void __launch_bounds__(256)
final_kernel(float* __restrict__ out, int Bn) {
    __shared__ float s_acol[NJ];
    __shared__ float s_red[8][4];
    const int tid = threadIdx.x;
    const int b   = blockIdx.x;
    if (tid < NJ) s_acol[tid] = g_acol[tid];
    __syncthreads();

    const float sc  = g_scale[tid];
    const float shf = g_shift[tid];
    const float* inb = g_bufA + (size_t)b * NJ * FD;

    float v = 0.f;
    #pragma unroll
    for (int r = 0; r < NJ; ++r) {
        float x = inb[r*FD + tid];
        x = fmaxf(fmaf(x, sc, shf), 0.f);
        v = fmaf(s_acol[r], x, v);
    }
    float4 w = ((const float4*)g_whc)[tid];
    float p0 = v * w.x, p1 = v * w.y, p2 = v * w.z, p3 = v * w.w;
    #pragma unroll
    for (int o = 16; o; o >>= 1) {
        p0 += __shfl_down_sync(0xffffffffu, p0, o);
        p1 += __shfl_down_sync(0xffffffffu, p1, o);
        p2 += __shfl_down_sync(0xffffffffu, p2, o);
        p3 += __shfl_down_sync(0xffffffffu, p3, o);
    }
    const int lane = tid & 31, wid = tid >> 5;
    if (lane == 0) { s_red[wid][0] = p0; s_red[wid][1] = p1; s_red[wid][2] = p2; s_red[wid][3] = p3; }
    __syncthreads();
    if (tid < 4) {
        float s = 0.f;
        #pragma unroll
        for (int w8 = 0; w8 < 8; ++w8) s += s_red[w8][tid];
        out[b*4 + tid] = s + g_bhc[tid];
    }
}

// ============================================================
extern "C" void kernel_launch(void* const* d_in, const int* in_sizes, int n_in,
                              void* d_out, int out_size) {
    const float* x   = (const float*)d_in[0];
    const float* w0  = (const float*)d_in[1];
    const float* b0  = (const float*)d_in[2];
    const float* gg0 = (const float*)d_in[3];
    const float* be0 = (const float*)d_in[4];
    const float* w1  = (const float*)d_in[5];
    const float* b1  = (const float*)d_in[6];
    const float* gg1 = (const float*)d_in[7];
    const float* be1 = (const float*)d_in[8];
    const float* w2  = (const float*)d_in[9];
    const float* b2  = (const float*)d_in[10];
    const float* gg2 = (const float*)d_in[11];
    const float* be2 = (const float*)d_in[12];
    const float* wh  = (const float*)d_in[13];
    const float* bh  = (const float*)d_in[14];
    const float* wc  = (const float*)d_in[15];
    const float* bc  = (const float*)d_in[16];
    const int*   src = (const int*)d_in[17];
    const int*   dst = (const int*)d_in[18];
    float* out = (float*)d_out;

    const int B   = in_sizes[0] / (NJ * FD);
    const int epg = in_sizes[17] / B;
    const float inv_nn = 1.0f / (float)(B * NJ);
    const int fused_grid = (B + 3) / 4;

    static int smem_set = 0;
    if (!smem_set) {
        cudaFuncSetAttribute(fused_kernel, cudaFuncAttributeMaxDynamicSharedMemorySize, FUSED_SMEM);
        smem_set = 1;
    }

    // fused_kernel is launch #4 (ncu capture slot).
    prep_kernel<<<1, 256>>>(src, dst, epg, wh, wc, bh, bc);
    convw_kernel<<<64, 256>>>(w0, 0);
    convw_kernel<<<64, 256>>>(w1, 1);

    fused_kernel<<<fused_grid, 512, FUSED_SMEM>>>(x, b0, 0, 0, B);
    stats_kernel<<<1, 256>>>(gg0, be0, inv_nn);
    convw_kernel<<<64, 256>>>(w2, 2);

    fused_kernel<<<fused_grid, 512, FUSED_SMEM>>>(x, b1, 1, 1, B);
    stats_kernel<<<1, 256>>>(gg1, be1, inv_nn);

    fused_kernel<<<fused_grid, 512, FUSED_SMEM>>>(x, b2, 1, 2, B);
    stats_kernel<<<1, 256>>>(gg2, be2, inv_nn);

    final_kernel<<<B, 256>>>(out, B);
}

// round 14
// speedup vs baseline: 1.2391x; 1.0427x over previous
#include <cuda_runtime.h>
#include <cuda_bf16.h>
#include <math.h>
#include <stdint.h>

#define NJ 33
#define FD 256
#define MAXB 4096
#define NNMAX (MAXB*NJ)
#define MAXE 165

typedef uint32_t u32;
typedef uint64_t u64;

// ---- scratch (no allocations allowed) ----
__device__ float g_bufA[(size_t)NNMAX*FD];
__device__ float g_sum[FD], g_sumsq[FD];
__device__ float g_scale[FD], g_shift[FD];
__device__ int   g_rp[NJ+1];
__device__ int   g_ci[MAXE];
__device__ float g_av[MAXE];
__device__ float g_acol[NJ];
__device__ float g_whc[FD*4];
__device__ float g_bhc[4];
// Weights pre-packed in m16n8k16 B-fragment order, bf16 hi/lo split.
__device__ u64 g_wb_hi[3][16384];
__device__ u64 g_wb_lo[3][16384];

// ============================================================
// Prep (parallelized CSR build)
// ============================================================
__global__ void prep_kernel(const int* __restrict__ src, const int* __restrict__ dst,
                            int epg,
                            const float* __restrict__ wh, const float* __restrict__ wc,
                            const float* __restrict__ bh, const float* __restrict__ bc) {
    __shared__ int   s_s[MAXE], s_d[MAXE];
    __shared__ float s_dinv[NJ];
    __shared__ int   s_cnt[NJ];
    const int tid = threadIdx.x;
    if (tid < epg && tid < MAXE) { s_s[tid] = src[tid]; s_d[tid] = dst[tid]; }
    if (tid < FD) { g_sum[tid] = 0.f; g_sumsq[tid] = 0.f; }
    __syncthreads();
    if (tid < NJ) {
        int d = 0;
        for (int e = 0; e < epg; ++e) d += (s_d[e] == tid);
        s_cnt[tid] = d;
        s_dinv[tid] = rsqrtf((float)d);
    }
    __syncthreads();
    if (tid == 0) {
        int pos = 0;
        for (int j = 0; j < NJ; ++j) { g_rp[j] = pos; pos += s_cnt[j]; }
        g_rp[NJ] = pos;
    }
    __syncthreads();
    if (tid < NJ) {
        int pos = g_rp[tid];
        float s = 0.f;
        for (int e = 0; e < epg; ++e) {
            if (s_d[e] == tid) {
                const int r = s_s[e];
                g_ci[pos] = r;
                g_av[pos] = s_dinv[r] * s_dinv[tid];
                pos++;
            }
            if (s_s[e] == tid) s += s_dinv[tid] * s_dinv[s_d[e]];
        }
        g_acol[tid] = s / (float)NJ;
    }
    for (int idx = tid; idx < FD*4; idx += blockDim.x) {
        int k = idx >> 2, l = idx & 3;
        float s = 0.f;
        for (int c = 0; c < FD; ++c) s += wh[k*FD + c] * wc[c*4 + l];
        g_whc[idx] = s;
    }
    if (tid < 4) {
        float s = 0.f;
        for (int c = 0; c < FD; ++c) s += bh[c] * wc[c*4 + tid];
        g_bhc[tid] = s + bc[tid];
    }
}

// W[k][n] fp32 -> fragment-ordered bf16 hi/lo pack.
__global__ void convw_kernel(const float* __restrict__ W, int layer) {
    const int i = blockIdx.x * 256 + threadIdx.x;       // 0..16383
    const int lane = i & 31;
    const int ks = (i >> 5) & 15;
    const int nf = i >> 9;
    const int n = nf*8 + (lane >> 2);
    const int k = ks*16 + (lane & 3)*2;
    float e0 = W[k*FD + n],     e1 = W[(k+1)*FD + n];
    float e2 = W[(k+8)*FD + n], e3 = W[(k+9)*FD + n];
    __nv_bfloat162 h0 = __floats2bfloat162_rn(e0, e1);
    __nv_bfloat162 h1 = __floats2bfloat162_rn(e2, e3);
    __nv_bfloat162 l0 = __floats2bfloat162_rn(e0 - __low2float(h0), e1 - __high2float(h0));
    __nv_bfloat162 l1 = __floats2bfloat162_rn(e2 - __low2float(h1), e3 - __high2float(h1));
    g_wb_hi[layer][i] = (u64)(*(u32*)&h0) | ((u64)(*(u32*)&h1) << 32);
    g_wb_lo[layer][i] = (u64)(*(u32*)&l0) | ((u64)(*(u32*)&l1) << 32);
}

// ============================================================
// Fully fused layer: pre(Z) @ W  then  A_hat @ Y + b, BN sums.
// Graph-major [g][j][f]: block = 4 graphs = 132 rows (pad 144).
// 16 warps = 1m x 16n; warp tile 144x16 (9 m16 x 2 n8 frags).
// MMA loop is TERM-MAJOR over mf-groups of 3: dependent reuses of
// an accumulator are >= 6 MMAs apart -> tensor pipe pipelines.
// ============================================================
#define ASTRIDE 272
#define A_HI 0
#define A_LO 39168          /* 144*272 */
#define SM_SC 147456        /* ybuf occupies [0,147456) after MMA */
#define SM_SH 148480
#define SM_RP 149504
#define SM_CI 149664
#define SM_AV 150328
#define FUSED_SMEM 151040

__device__ __forceinline__ void mma16816(float* d, u32 a0, u32 a1, u32 a2, u32 a3,
                                         u32 b0, u32 b1) {
    asm volatile(
        "mma.sync.aligned.m16n8k16.row.col.f32.bf16.bf16.f32 "
        "{%0,%1,%2,%3}, {%4,%5,%6,%7}, {%8,%9}, {%0,%1,%2,%3};"
        : "+f"(d[0]), "+f"(d[1]), "+f"(d[2]), "+f"(d[3])
        : "r"(a0), "r"(a1), "r"(a2), "r"(a3), "r"(b0), "r"(b1));
}

__global__ void __launch_bounds__(512)
fused_kernel(const float* __restrict__ x_ext, const float* __restrict__ bias,
             int in_sel /*0 = x + nan_to_num, 1 = g_bufA + BN+relu*/,
             int layer, int Bn) {
    extern __shared__ char smem[];
    const int tid  = threadIdx.x;
    const int lane = tid & 31, wid = tid >> 5;     // 16 warps
    const int wn   = wid;                           // n stripe: cols [wn*16, wn*16+16)
    const int blk  = blockIdx.x;
    const int m0   = blk * 132;                     // global row base (graph-major)
    const int NNv  = Bn * NJ;
    const int mode = in_sel;

    const float* in = (in_sel == 0) ? x_ext : (const float*)g_bufA;

    // stage BN params + CSR into smem (regions above ybuf; persist whole kernel)
    if (tid < 256) {
        *(float*)(smem + SM_SC + tid*4) = g_scale[tid];
        *(float*)(smem + SM_SH + tid*4) = g_shift[tid];
    }
    if (tid <= NJ) *(int*)(smem + SM_RP + tid*4) = g_rp[tid];
    if (tid < MAXE) {
        *(int*)  (smem + SM_CI + tid*4) = g_ci[tid];
        *(float*)(smem + SM_AV + tid*4) = g_av[tid];
    }

    float acc[9][2][4];
    #pragma unroll
    for (int mf = 0; mf < 9; ++mf)
        #pragma unroll
        for (int nf = 0; nf < 2; ++nf)
            #pragma unroll
            for (int q = 0; q < 4; ++q) acc[mf][nf][q] = 0.f;

    const u64* __restrict__ WBH = g_wb_hi[layer];
    const u64* __restrict__ WBL = g_wb_lo[layer];

    const int rowl = tid >> 2, qc = tid & 3;        // loader: 128 rows x 4 quarters
    const float* ssc = (const float*)(smem + SM_SC);
    const float* ssh = (const float*)(smem + SM_SH);

    const int arowb = (lane >> 2);
    const int acol  = (lane & 3)*4;                 // bytes within k16 step

    for (int c = 0; c < 2; ++c) {
        __syncthreads();
        // ---- stage A: rows 0..143 (132 valid), k in [c*128, +128) ----
        #pragma unroll
        for (int rr = 0; rr < 2; ++rr) {
            const int r = rowl + rr*128;
            if (rr == 1 && rowl >= 16) break;
            const bool ok = (r < 132) && (m0 + r < NNv);
            char* hib = smem + A_HI + r*ASTRIDE + qc*64;
            char* lob = smem + A_LO + r*ASTRIDE + qc*64;
            const float* srcrow = in + (size_t)(m0 + r) * FD;
            #pragma unroll
            for (int i = 0; i < 8; ++i) {
                const int k = c*128 + qc*32 + i*4;
                float4 v = make_float4(0.f, 0.f, 0.f, 0.f);
                if (ok) {
                    v = *(const float4*)(srcrow + k);
                    if (mode == 0) {
                        if (v.x != v.x) v.x = 0.f;
                        if (v.y != v.y) v.y = 0.f;
                        if (v.z != v.z) v.z = 0.f;
                        if (v.w != v.w) v.w = 0.f;
                    } else {
                        v.x = fmaxf(fmaf(v.x, ssc[k],   ssh[k]),   0.f);
                        v.y = fmaxf(fmaf(v.y, ssc[k+1], ssh[k+1]), 0.f);
                        v.z = fmaxf(fmaf(v.z, ssc[k+2], ssh[k+2]), 0.f);
                        v.w = fmaxf(fmaf(v.w, ssc[k+3], ssh[k+3]), 0.f);
                    }
                }
                __nv_bfloat162 h0 = __floats2bfloat162_rn(v.x, v.y);
                __nv_bfloat162 h1 = __floats2bfloat162_rn(v.z, v.w);
                __nv_bfloat162 l0 = __floats2bfloat162_rn(v.x - __low2float(h0), v.y - __high2float(h0));
                __nv_bfloat162 l1 = __floats2bfloat162_rn(v.z - __low2float(h1), v.w - __high2float(h1));
                *(u32*)(hib + i*8)     = *(u32*)&h0;
                *(u32*)(hib + i*8 + 4) = *(u32*)&h1;
                *(u32*)(lob + i*8)     = *(u32*)&l0;
                *(u32*)(lob + i*8 + 4) = *(u32*)&l1;
            }
        }
        __syncthreads();

        for (int ks = 0; ks < 8; ++ks) {
            const int ksa = c*8 + ks;
            const u64 vh0 = WBH[((wn*2 + 0)*16 + ksa)*32 + lane];
            const u64 vl0 = WBL[((wn*2 + 0)*16 + ksa)*32 + lane];
            const u64 vh1 = WBH[((wn*2 + 1)*16 + ksa)*32 + lane];
            const u64 vl1 = WBL[((wn*2 + 1)*16 + ksa)*32 + lane];
            const u32 bh0 = (u32)vh0, bh0b = (u32)(vh0 >> 32);
            const u32 bl0 = (u32)vl0, bl0b = (u32)(vl0 >> 32);
            const u32 bh1 = (u32)vh1, bh1b = (u32)(vh1 >> 32);
            const u32 bl1 = (u32)vl1, bl1b = (u32)(vl1 >> 32);

            #pragma unroll
            for (int mg = 0; mg < 3; ++mg) {
                // load A fragments for 3 m-tiles (hi + lo)
                u32 AH[3][4], AL[3][4];
                #pragma unroll
                for (int mm = 0; mm < 3; ++mm) {
                    const int ro = ((mg*3 + mm)*16 + arowb)*ASTRIDE + ks*32 + acol;
                    AH[mm][0] = *(const u32*)(smem + A_HI + ro);
                    AH[mm][1] = *(const u32*)(smem + A_HI + ro + 8*ASTRIDE);
                    AH[mm][2] = *(const u32*)(smem + A_HI + ro + 16);
                    AH[mm][3] = *(const u32*)(smem + A_HI + ro + 8*ASTRIDE + 16);
                    AL[mm][0] = *(const u32*)(smem + A_LO + ro);
                    AL[mm][1] = *(const u32*)(smem + A_LO + ro + 8*ASTRIDE);
                    AL[mm][2] = *(const u32*)(smem + A_LO + ro + 16);
                    AL[mm][3] = *(const u32*)(smem + A_LO + ro + 8*ASTRIDE + 16);
                }
                // term 1: hi * b_hi   (6 independent accs in flight)
                #pragma unroll
                for (int mm = 0; mm < 3; ++mm) {
                    mma16816(acc[mg*3+mm][0], AH[mm][0], AH[mm][1], AH[mm][2], AH[mm][3], bh0, bh0b);
                    mma16816(acc[mg*3+mm][1], AH[mm][0], AH[mm][1], AH[mm][2], AH[mm][3], bh1, bh1b);
                }
                // term 2: hi * b_lo
                #pragma unroll
                for (int mm = 0; mm < 3; ++mm) {
                    mma16816(acc[mg*3+mm][0], AH[mm][0], AH[mm][1], AH[mm][2], AH[mm][3], bl0, bl0b);
                    mma16816(acc[mg*3+mm][1], AH[mm][0], AH[mm][1], AH[mm][2], AH[mm][3], bl1, bl1b);
                }
                // term 3: lo * b_hi
                #pragma unroll
                for (int mm = 0; mm < 3; ++mm) {
                    mma16816(acc[mg*3+mm][0], AL[mm][0], AL[mm][1], AL[mm][2], AL[mm][3], bh0, bh0b);
                    mma16816(acc[mg*3+mm][1], AL[mm][0], AL[mm][1], AL[mm][2], AL[mm][3], bh1, bh1b);
                }
            }
        }
    }

    // ---- stage Y into smem (overwrites A region) ----
    __syncthreads();
    float2* yb = (float2*)smem;                     // [row*128 + colpair], 144 rows
    const int cpb = wn*8 + (lane & 3);
    #pragma unroll
    for (int mf = 0; mf < 9; ++mf) {
        const int r0 = mf*16 + arowb;
        #pragma unroll
        for (int nf = 0; nf < 2; ++nf) {
            const int cpi = cpb + nf*4;
            yb[ r0     *128 + cpi] = make_float2(acc[mf][nf][0], acc[mf][nf][1]);
            yb[(r0 + 8)*128 + cpi] = make_float2(acc[mf][nf][2], acc[mf][nf][3]);
        }
    }
    __syncthreads();

    // ---- sparse A_hat epilogue + bias + BN sums ----
    const int cp = tid & 127, gi = tid >> 7;        // 4 graphs, 128 col-pairs
    const int g0 = blk*4 + gi;
    if (g0 < Bn) {
        const int*   srp = (const int*)(smem + SM_RP);
        const int*   sci = (const int*)(smem + SM_CI);
        const float* sav = (const float*)(smem + SM_AV);
        const float2 bia = ((const float2*)bias)[cp];
        float s1x = 0.f, s1y = 0.f, s2x = 0.f, s2y = 0.f;
        float* outg = g_bufA + (size_t)(m0 + gi*NJ) * FD;
        for (int j = 0; j < NJ; ++j) {
            float zx = bia.x, zy = bia.y;
            const int p1 = srp[j+1];
            for (int p = srp[j]; p < p1; ++p) {
                const float  a = sav[p];
                const float2 y = yb[(gi*NJ + sci[p])*128 + cp];
                zx = fmaf(a, y.x, zx);
                zy = fmaf(a, y.y, zy);
            }
            *(float2*)(outg + j*FD + cp*2) = make_float2(zx, zy);
            s1x += zx; s1y += zy;
            s2x = fmaf(zx, zx, s2x); s2y = fmaf(zy, zy, s2y);
        }
        atomicAdd(&g_sum[2*cp],     s1x);
        atomicAdd(&g_sum[2*cp + 1], s1y);
        atomicAdd(&g_sumsq[2*cp],     s2x);
        atomicAdd(&g_sumsq[2*cp + 1], s2y);
    }
}

// ============================================================
__global__ void stats_kernel(const float* __restrict__ g, const float* __restrict__ be,
                             float inv_nn) {
    int tid = threadIdx.x;
    float mu  = g_sum[tid] * inv_nn;
    float var = g_sumsq[tid] * inv_nn - mu * mu;
    float rs  = rsqrtf(var + 1e-5f);
    float sc  = rs * g[tid];
    g_scale[tid] = sc;
    g_shift[tid] = be[tid] - mu * sc;
    g_sum[tid] = 0.f; g_sumsq[tid] = 0.f;
}

// ============================================================
// Head: BN2+ReLU -> a_col^T h (per graph, graph-major) -> whc + bhc
// ============================================================
__global__ void __launch_bounds__(256)
final_kernel(float* __restrict__ out, int Bn) {
    __shared__ float s_acol[NJ];
    __shared__ float s_red[8][4];
    const int tid = threadIdx.x;
    const int b   = blockIdx.x;
    if (tid < NJ) s_acol[tid] = g_acol[tid];
    __syncthreads();

    const float sc  = g_scale[tid];
    const float shf = g_shift[tid];
    const float* inb = g_bufA + (size_t)b * NJ * FD;

    float v = 0.f;
    #pragma unroll
    for (int r = 0; r < NJ; ++r) {
        float x = inb[r*FD + tid];
        x = fmaxf(fmaf(x, sc, shf), 0.f);
        v = fmaf(s_acol[r], x, v);
    }
    float4 w = ((const float4*)g_whc)[tid];
    float p0 = v * w.x, p1 = v * w.y, p2 = v * w.z, p3 = v * w.w;
    #pragma unroll
    for (int o = 16; o; o >>= 1) {
        p0 += __shfl_down_sync(0xffffffffu, p0, o);
        p1 += __shfl_down_sync(0xffffffffu, p1, o);
        p2 += __shfl_down_sync(0xffffffffu, p2, o);
        p3 += __shfl_down_sync(0xffffffffu, p3, o);
    }
    const int lane = tid & 31, wid = tid >> 5;
    if (lane == 0) { s_red[wid][0] = p0; s_red[wid][1] = p1; s_red[wid][2] = p2; s_red[wid][3] = p3; }
    __syncthreads();
    if (tid < 4) {
        float s = 0.f;
        #pragma unroll
        for (int w8 = 0; w8 < 8; ++w8) s += s_red[w8][tid];
        out[b*4 + tid] = s + g_bhc[tid];
    }
}

// ============================================================
extern "C" void kernel_launch(void* const* d_in, const int* in_sizes, int n_in,
                              void* d_out, int out_size) {
    const float* x   = (const float*)d_in[0];
    const float* w0  = (const float*)d_in[1];
    const float* b0  = (const float*)d_in[2];
    const float* gg0 = (const float*)d_in[3];
    const float* be0 = (const float*)d_in[4];
    const float* w1  = (const float*)d_in[5];
    const float* b1  = (const float*)d_in[6];
    const float* gg1 = (const float*)d_in[7];
    const float* be1 = (const float*)d_in[8];
    const float* w2  = (const float*)d_in[9];
    const float* b2  = (const float*)d_in[10];
    const float* gg2 = (const float*)d_in[11];
    const float* be2 = (const float*)d_in[12];
    const float* wh  = (const float*)d_in[13];
    const float* bh  = (const float*)d_in[14];
    const float* wc  = (const float*)d_in[15];
    const float* bc  = (const float*)d_in[16];
    const int*   src = (const int*)d_in[17];
    const int*   dst = (const int*)d_in[18];
    float* out = (float*)d_out;

    const int B   = in_sizes[0] / (NJ * FD);
    const int epg = in_sizes[17] / B;
    const float inv_nn = 1.0f / (float)(B * NJ);
    const int fused_grid = (B + 3) / 4;

    static int smem_set = 0;
    if (!smem_set) {
        cudaFuncSetAttribute(fused_kernel, cudaFuncAttributeMaxDynamicSharedMemorySize, FUSED_SMEM);
        smem_set = 1;
    }

    // fused_kernel is launch #4 (ncu capture slot).
    prep_kernel<<<1, 256>>>(src, dst, epg, wh, wc, bh, bc);
    convw_kernel<<<64, 256>>>(w0, 0);
    convw_kernel<<<64, 256>>>(w1, 1);

    fused_kernel<<<fused_grid, 512, FUSED_SMEM>>>(x, b0, 0, 0, B);
    stats_kernel<<<1, 256>>>(gg0, be0, inv_nn);
    convw_kernel<<<64, 256>>>(w2, 2);

    fused_kernel<<<fused_grid, 512, FUSED_SMEM>>>(x, b1, 1, 1, B);
    stats_kernel<<<1, 256>>>(gg1, be1, inv_nn);

    fused_kernel<<<fused_grid, 512, FUSED_SMEM>>>(x, b2, 1, 2, B);
    stats_kernel<<<1, 256>>>(gg2, be2, inv_nn);

    final_kernel<<<B, 256>>>(out, B);
}